// round 14
// baseline (speedup 1.0000x reference)
#include <cuda_runtime.h>
#include <math.h>
#include <stdint.h>

#define N_NODES   50000
#define N_EDGES   800000
#define NF        96
#define NH        128
#define NC        40
#define GROWS     64                    // rows per GEMM block
#define SCAN_B    1024
#define NB1       ((N_NODES + SCAN_B - 1) / SCAN_B)   // 49

// ---------------- device scratch (static, allocation-free) ----------------
// Symbols referenced ONLY from device code (host-side use gives shadow addr).
__device__ __align__(16) float g_t   [N_NODES * NC];  // norm*feat@M2^T, prop state
__device__ __align__(16) float g_acc [N_NODES * NC];  // hop-1 result
__device__ float g_norm[N_NODES];
__device__ int   g_deg  [N_NODES];
__device__ int   g_off  [N_NODES];
__device__ int   g_cursor[N_NODES];
__device__ int   g_bsum [NB1];
__device__ int   g_csr  [N_EDGES];                    // src ids grouped by dst
__device__ float g_M1p[4 * NF * NC];                  // K-split partials, [f][c]
__device__ float g_M2p[4 * NF * NC];

// ---------------------------------------------------------------------------
__global__ void k_init() {
    int i = blockIdx.x * blockDim.x + threadIdx.x;
    if (i < N_NODES) g_deg[i] = 0;
}

__global__ void k_deg(const int* __restrict__ dst) {
    int e = blockIdx.x * blockDim.x + threadIdx.x;
    if (e < N_EDGES) atomicAdd(&g_deg[dst[e]], 1);
}

// Level-1 scan: per-1024-block exclusive scan of g_deg -> g_off, block sums -> g_bsum
__global__ void k_scan1() {
    __shared__ int sh[SCAN_B];
    int i = blockIdx.x * SCAN_B + threadIdx.x;
    int v = (i < N_NODES) ? g_deg[i] : 0;
    sh[threadIdx.x] = v;
    __syncthreads();
    for (int off = 1; off < SCAN_B; off <<= 1) {
        int t = (threadIdx.x >= off) ? sh[threadIdx.x - off] : 0;
        __syncthreads();
        sh[threadIdx.x] += t;
        __syncthreads();
    }
    if (i < N_NODES) g_off[i] = sh[threadIdx.x] - v;      // exclusive, block-local
    if (threadIdx.x == SCAN_B - 1) g_bsum[blockIdx.x] = sh[SCAN_B - 1];
}

// Level-2 carry folded in: each 256-node block (aligned within one 1024-scan-block)
// sums the preceding g_bsum entries itself. Also finalizes cursors + norms.
__global__ void k_scan3() {
    __shared__ int carry_sh;
    if (threadIdx.x == 0) {
        int sb = (blockIdx.x * 256) >> 10;    // same for all 256 nodes (aligned)
        int c = 0;
#pragma unroll 8
        for (int j = 0; j < sb; j++) c += g_bsum[j];
        carry_sh = c;
    }
    __syncthreads();
    int i = blockIdx.x * 256 + threadIdx.x;
    if (i >= N_NODES) return;
    int off = g_off[i] + carry_sh;
    g_off[i] = off;
    g_cursor[i] = off;
    int d = g_deg[i];
    g_norm[i] = (d > 0) ? rsqrtf((float)d) : 1.0f;
}

__global__ void k_fill(const int* __restrict__ src, const int* __restrict__ dst) {
    int e = blockIdx.x * blockDim.x + threadIdx.x;
    if (e >= N_EDGES) return;
    int d = dst[e];
    int pos = atomicAdd(&g_cursor[d], 1);
    g_csr[pos] = src[e];
}

// Folded projection weights, K-split 4x for latency hiding.
// M1[c,f] = sum_h Wp[c,h]     * W_lin[h,f]
// M2[c,f] = sum_h Wp[c,128+h] * W_sgc[h,f]
__global__ void k_weights(const float* __restrict__ Wp,
                          const float* __restrict__ Wsgc,
                          const float* __restrict__ Wlin) {
    int c    = blockIdx.x;        // 0..39
    int sel  = blockIdx.y;        // 0 -> M1, 1 -> M2
    int part = blockIdx.z;        // 0..3, 32 h each
    int f    = threadIdx.x;       // 0..95
    const float* wp = Wp + c * 256 + sel * 128 + part * 32;
    const float* W  = (sel ? Wsgc : Wlin) + part * 32 * NF;
    float acc = 0.0f;
#pragma unroll
    for (int h = 0; h < 32; h++)
        acc = fmaf(__ldg(wp + h), __ldg(W + h * NF + f), acc);
    (sel ? g_M2p : g_M1p)[part * (NF * NC) + f * NC + c] = acc;
}

__device__ __forceinline__ void fma4(float4& a, float s, const float4 m) {
    a.x = fmaf(s, m.x, a.x);
    a.y = fmaf(s, m.y, a.y);
    a.z = fmaf(s, m.z, a.z);
    a.w = fmaf(s, m.w, a.w);
}
__device__ __forceinline__ void add4(float4& a, const float4 b) {
    a.x += b.x; a.y += b.y; a.z += b.z; a.w += b.w;
}

// Fused dual GEMM, 4 rows x 4 cols x 2 matrices per thread (LDS-traffic optimized):
//   out[v,:] = feat[v,:] @ M1^T            (base term, straight to d_out)
//   g_t[v,:] = norm[v] * (feat[v,:]@M2^T)  (pre-scaled propagation input)
// Dynamic smem: sM1 3840 + sM2 3840 + sF 64*97 floats = 55552 bytes.
__global__ void __launch_bounds__(160) k_gemm(const float* __restrict__ feat,
                                              float* __restrict__ out) {
    extern __shared__ float sh[];
    float* sM1 = sh;                    // [NF*NC]
    float* sM2 = sh + NF * NC;          // [NF*NC]
    float* sF  = sh + 2 * NF * NC;      // [GROWS*97]

    const int tid = threadIdx.y * 10 + threadIdx.x;
    for (int i = tid; i < NF * NC; i += 160) {
        sM1[i] = g_M1p[i] + g_M1p[i + 3840] + g_M1p[i + 7680] + g_M1p[i + 11520];
        sM2[i] = g_M2p[i] + g_M2p[i + 3840] + g_M2p[i + 7680] + g_M2p[i + 11520];
    }

    const int row0 = blockIdx.x * GROWS;
    for (int i = tid; i < GROWS * NF; i += 160) {
        int r = i / NF, f = i - r * NF;
        int v = row0 + r;
        sF[r * 97 + f] = (v < N_NODES) ? feat[(size_t)v * NF + f] : 0.0f;
    }
    __syncthreads();

    const int cx = threadIdx.x;            // col group: 4*cx .. 4*cx+3
    const int r0 = threadIdx.y * 4;        // rows r0 .. r0+3

    float4 a1[4], a2[4];
#pragma unroll
    for (int r = 0; r < 4; r++) { a1[r] = make_float4(0, 0, 0, 0); a2[r] = a1[r]; }

#pragma unroll 4
    for (int f = 0; f < NF; f++) {
        const float4 m1 = *reinterpret_cast<const float4*>(sM1 + f * NC + cx * 4);
        const float4 m2 = *reinterpret_cast<const float4*>(sM2 + f * NC + cx * 4);
#pragma unroll
        for (int r = 0; r < 4; r++) {
            const float fv = sF[(r0 + r) * 97 + f];
            fma4(a1[r], fv, m1);
            fma4(a2[r], fv, m2);
        }
    }

#pragma unroll
    for (int r = 0; r < 4; r++) {
        const int v = row0 + r0 + r;
        if (v < N_NODES) {
            float n = g_norm[v];
            *reinterpret_cast<float4*>(out + (size_t)v * NC + cx * 4) = a1[r];
            float4 t = a2[r]; t.x *= n; t.y *= n; t.z *= n; t.w *= n;
            *reinterpret_cast<float4*>(g_t + (size_t)v * NC + cx * 4) = t;
        }
    }
}

// Hop 1 (CSR gather, chunk-parallel): 10 lanes per node, one float4 each.
// Per edge, the 10-lane group loads one contiguous 160B source row (coalesced);
// the csr index load is a same-address broadcast. Output store fully coalesced.
// g_acc[v,:] = n[v]^2 * sum_{s in in(v)} g_t[s,:]
__global__ void k_gather1() {
    int t = blockIdx.x * blockDim.x + threadIdx.x;
    if (t >= N_NODES * 10) return;
    int v = t / 10;
    int c = t - v * 10;
    int beg = __ldg(&g_off[v]);
    int deg = __ldg(&g_deg[v]);
    const int* cp = g_csr + beg;
    float4 a = make_float4(0, 0, 0, 0);
#pragma unroll 4
    for (int i = 0; i < deg; i++) {
        int s = __ldg(cp + i);
        add4(a, *reinterpret_cast<const float4*>(g_t + (size_t)s * NC + c * 4));
    }
    float n = __ldg(&g_norm[v]);
    float s2 = n * n;
    a.x *= s2; a.y *= s2; a.z *= s2; a.w *= s2;
    reinterpret_cast<float4*>(g_acc)[t] = a;
}

// Hop 2 + epilogue: out[v,:] += n[v] * sum_{s in in(v)} g_acc[s,:]
__global__ void k_gather2(float* __restrict__ out) {
    int t = blockIdx.x * blockDim.x + threadIdx.x;
    if (t >= N_NODES * 10) return;
    int v = t / 10;
    int c = t - v * 10;
    int beg = __ldg(&g_off[v]);
    int deg = __ldg(&g_deg[v]);
    const int* cp = g_csr + beg;
    float4 a = make_float4(0, 0, 0, 0);
#pragma unroll 4
    for (int i = 0; i < deg; i++) {
        int s = __ldg(cp + i);
        add4(a, *reinterpret_cast<const float4*>(g_acc + (size_t)s * NC + c * 4));
    }
    float n = __ldg(&g_norm[v]);
    float4* po = reinterpret_cast<float4*>(out) + t;
    float4 b = *po;
    b.x = fmaf(n, a.x, b.x);
    b.y = fmaf(n, a.y, b.y);
    b.z = fmaf(n, a.z, b.z);
    b.w = fmaf(n, a.w, b.w);
    *po = b;
}

// ---------------------------------------------------------------------------
extern "C" void kernel_launch(void* const* d_in, const int* in_sizes, int n_in,
                              void* d_out, int out_size) {
    const float* feat  = (const float*)d_in[0];   // [50000, 96]
    const int*   src   = (const int*)  d_in[1];   // [800000]
    const int*   dst   = (const int*)  d_in[2];   // [800000]
    const float* Wsgc  = (const float*)d_in[3];   // [128, 96]
    const float* Wlin  = (const float*)d_in[4];   // [128, 96]
    const float* Wproj = (const float*)d_in[5];   // [40, 256]
    float* out = (float*)d_out;                   // [50000, 40]

    const int gemm_smem = (2 * NF * NC + GROWS * 97) * (int)sizeof(float); // 55552
    cudaFuncSetAttribute(k_gemm, cudaFuncAttributeMaxDynamicSharedMemorySize, gemm_smem);

    k_init<<<(N_NODES + 255) / 256, 256>>>();
    k_deg <<<(N_EDGES + 255) / 256, 256>>>(dst);
    k_scan1<<<NB1, SCAN_B>>>();
    k_scan3<<<(N_NODES + 255) / 256, 256>>>();
    k_fill<<<(N_EDGES + 255) / 256, 256>>>(src, dst);
    k_weights<<<dim3(NC, 2, 4), NF>>>(Wproj, Wsgc, Wlin);
    k_gemm<<<(N_NODES + GROWS - 1) / GROWS, dim3(10, 16), gemm_smem>>>(feat, out);
    k_gather1<<<(N_NODES * 10 + 255) / 256, 256>>>();
    k_gather2<<<(N_NODES * 10 + 255) / 256, 256>>>(out);
}

// round 15
// speedup vs baseline: 1.0839x; 1.0839x over previous
#include <cuda_runtime.h>
#include <cuda_bf16.h>
#include <math.h>
#include <stdint.h>

#define N_NODES   50000
#define N_EDGES   800000
#define NF        96
#define NH        128
#define NC        40
#define GROWS     64                    // rows per GEMM block

// ---------------- device scratch (static, allocation-free) ----------------
// Symbols referenced ONLY from device code (host-side use gives shadow addr).
__device__ __align__(16) __nv_bfloat16 g_t  [N_NODES * NC];  // prop state (bf16)
__device__ __align__(16) __nv_bfloat16 g_acc[N_NODES * NC];  // hop-1 result (bf16)
__device__ float g_norm[N_NODES];
__device__ int   g_deg   [N_NODES];
__device__ int   g_off   [N_NODES];
__device__ int   g_cursor[N_NODES];
__device__ int   g_total;
__device__ int   g_csr   [N_EDGES];                  // src ids grouped by dst
__device__ float g_M1p[4 * NF * NC];                 // K-split partials, [f][c]
__device__ float g_M2p[4 * NF * NC];

// ---------------------------------------------------------------------------
__global__ void k_init() {
    int i = blockIdx.x * blockDim.x + threadIdx.x;
    if (i < N_NODES) g_deg[i] = 0;
    if (i == 0)      g_total = 0;
}

__global__ void k_deg(const int* __restrict__ dst) {
    int e = blockIdx.x * blockDim.x + threadIdx.x;
    if (e < N_EDGES) atomicAdd(&g_deg[dst[e]], 1);
}

// Single-pass region assignment: block-local exclusive scan + atomic region
// reservation (CSR regions need to be disjoint, not id-ordered). Also emits
// cursors + norms. Replaces the old two-kernel scan.
__global__ void k_scan() {
    __shared__ int sh[256];
    __shared__ int base_sh;
    int i = blockIdx.x * 256 + threadIdx.x;
    int d = (i < N_NODES) ? g_deg[i] : 0;
    sh[threadIdx.x] = d;
    __syncthreads();
#pragma unroll
    for (int off = 1; off < 256; off <<= 1) {
        int t = (threadIdx.x >= off) ? sh[threadIdx.x - off] : 0;
        __syncthreads();
        sh[threadIdx.x] += t;
        __syncthreads();
    }
    if (threadIdx.x == 255) base_sh = atomicAdd(&g_total, sh[255]);
    __syncthreads();
    if (i < N_NODES) {
        int off = base_sh + sh[threadIdx.x] - d;   // exclusive within block + base
        g_off[i] = off;
        g_cursor[i] = off;
        g_norm[i] = (d > 0) ? rsqrtf((float)d) : 1.0f;
    }
}

__global__ void k_fill(const int* __restrict__ src, const int* __restrict__ dst) {
    int e = blockIdx.x * blockDim.x + threadIdx.x;
    if (e >= N_EDGES) return;
    int d = dst[e];
    int pos = atomicAdd(&g_cursor[d], 1);
    g_csr[pos] = src[e];
}

// Folded projection weights, K-split 4x for latency hiding.
// M1[c,f] = sum_h Wp[c,h]     * W_lin[h,f]
// M2[c,f] = sum_h Wp[c,128+h] * W_sgc[h,f]
__global__ void k_weights(const float* __restrict__ Wp,
                          const float* __restrict__ Wsgc,
                          const float* __restrict__ Wlin) {
    int c    = blockIdx.x;        // 0..39
    int sel  = blockIdx.y;        // 0 -> M1, 1 -> M2
    int part = blockIdx.z;        // 0..3, 32 h each
    int f    = threadIdx.x;       // 0..95
    const float* wp = Wp + c * 256 + sel * 128 + part * 32;
    const float* W  = (sel ? Wsgc : Wlin) + part * 32 * NF;
    float acc = 0.0f;
#pragma unroll
    for (int h = 0; h < 32; h++)
        acc = fmaf(__ldg(wp + h), __ldg(W + h * NF + f), acc);
    (sel ? g_M2p : g_M1p)[part * (NF * NC) + f * NC + c] = acc;
}

// ---- packed f32x2 helpers (FFMA2 — ptxas never emits this from C++) ----
__device__ __forceinline__ unsigned long long bcast2(float s) {
    unsigned long long r;
    asm("mov.b64 %0, {%1, %1};" : "=l"(r) : "f"(s));
    return r;
}
__device__ __forceinline__ void ffma2(unsigned long long& d,
                                      unsigned long long a,
                                      unsigned long long b) {
    asm("fma.rn.f32x2 %0, %1, %2, %0;" : "+l"(d) : "l"(a), "l"(b));
}
__device__ __forceinline__ float2 unpack2(unsigned long long v) {
    float2 f;
    asm("mov.b64 {%0, %1}, %2;" : "=f"(f.x), "=f"(f.y) : "l"(v));
    return f;
}

// Fused dual GEMM (packed f32x2 mainloop), 4 rows x 4 cols x 2 matrices/thread:
//   out[v,:] = feat[v,:] @ M1^T            (base term fp32, straight to d_out)
//   g_t[v,:] = bf16( norm[v] * (feat[v,:]@M2^T) )
__global__ void __launch_bounds__(160) k_gemm(const float* __restrict__ feat,
                                              float* __restrict__ out) {
    extern __shared__ float sh[];
    float* sM1 = sh;                    // [NF*NC]
    float* sM2 = sh + NF * NC;          // [NF*NC]
    float* sF  = sh + 2 * NF * NC;      // [GROWS*97]

    const int tid = threadIdx.y * 10 + threadIdx.x;
    for (int i = tid; i < NF * NC; i += 160) {
        sM1[i] = g_M1p[i] + g_M1p[i + 3840] + g_M1p[i + 7680] + g_M1p[i + 11520];
        sM2[i] = g_M2p[i] + g_M2p[i + 3840] + g_M2p[i + 7680] + g_M2p[i + 11520];
    }

    const int row0 = blockIdx.x * GROWS;
    for (int i = tid; i < GROWS * NF; i += 160) {
        int r = i / NF, f = i - r * NF;
        int v = row0 + r;
        sF[r * 97 + f] = (v < N_NODES) ? feat[(size_t)v * NF + f] : 0.0f;
    }
    __syncthreads();

    const int cx = threadIdx.x;            // col group: 4*cx .. 4*cx+3
    const int r0 = threadIdx.y * 4;        // rows r0 .. r0+3

    unsigned long long a1lo[4] = {0, 0, 0, 0}, a1hi[4] = {0, 0, 0, 0};
    unsigned long long a2lo[4] = {0, 0, 0, 0}, a2hi[4] = {0, 0, 0, 0};

#pragma unroll 4
    for (int f = 0; f < NF; f++) {
        const ulonglong2 m1 = *reinterpret_cast<const ulonglong2*>(sM1 + f * NC + cx * 4);
        const ulonglong2 m2 = *reinterpret_cast<const ulonglong2*>(sM2 + f * NC + cx * 4);
#pragma unroll
        for (int r = 0; r < 4; r++) {
            const unsigned long long fb = bcast2(sF[(r0 + r) * 97 + f]);
            ffma2(a1lo[r], fb, m1.x);
            ffma2(a1hi[r], fb, m1.y);
            ffma2(a2lo[r], fb, m2.x);
            ffma2(a2hi[r], fb, m2.y);
        }
    }

#pragma unroll
    for (int r = 0; r < 4; r++) {
        const int v = row0 + r0 + r;
        if (v < N_NODES) {
            float n = g_norm[v];
            float2 x0 = unpack2(a1lo[r]), x1 = unpack2(a1hi[r]);
            *reinterpret_cast<float4*>(out + (size_t)v * NC + cx * 4) =
                make_float4(x0.x, x0.y, x1.x, x1.y);
            float2 y0 = unpack2(a2lo[r]), y1 = unpack2(a2hi[r]);
            __nv_bfloat162 b0 = __float22bfloat162_rn(make_float2(y0.x * n, y0.y * n));
            __nv_bfloat162 b1 = __float22bfloat162_rn(make_float2(y1.x * n, y1.y * n));
            uint2 u;
            u.x = *reinterpret_cast<unsigned int*>(&b0);
            u.y = *reinterpret_cast<unsigned int*>(&b1);
            *reinterpret_cast<uint2*>(g_t + (size_t)v * NC + cx * 4) = u;
        }
    }
}

__device__ __forceinline__ void acc_bf16x8(float* a, uint4 p) {
    float2 f;
    f = __bfloat1622float2(*reinterpret_cast<__nv_bfloat162*>(&p.x)); a[0] += f.x; a[1] += f.y;
    f = __bfloat1622float2(*reinterpret_cast<__nv_bfloat162*>(&p.y)); a[2] += f.x; a[3] += f.y;
    f = __bfloat1622float2(*reinterpret_cast<__nv_bfloat162*>(&p.z)); a[4] += f.x; a[5] += f.y;
    f = __bfloat1622float2(*reinterpret_cast<__nv_bfloat162*>(&p.w)); a[6] += f.x; a[7] += f.y;
}

// Hop 1 (CSR gather, chunk-parallel, bf16 source): 5 lanes per node, 8 classes
// each. Per edge the 5-lane group loads one contiguous 80B bf16 row; fp32
// accumulate; store back as bf16 with n^2 folded in.
__global__ void k_gather1() {
    int t = blockIdx.x * blockDim.x + threadIdx.x;
    if (t >= N_NODES * 5) return;
    int v = t / 5;
    int c = t - v * 5;
    int beg = __ldg(&g_off[v]);
    int deg = __ldg(&g_deg[v]);
    const int* cp = g_csr + beg;
    float a[8] = {0, 0, 0, 0, 0, 0, 0, 0};
#pragma unroll 4
    for (int i = 0; i < deg; i++) {
        int s = __ldg(cp + i);
        acc_bf16x8(a, *reinterpret_cast<const uint4*>(g_t + (size_t)s * NC + c * 8));
    }
    float n = __ldg(&g_norm[v]);
    float s2 = n * n;
    __nv_bfloat162 b0 = __float22bfloat162_rn(make_float2(a[0] * s2, a[1] * s2));
    __nv_bfloat162 b1 = __float22bfloat162_rn(make_float2(a[2] * s2, a[3] * s2));
    __nv_bfloat162 b2 = __float22bfloat162_rn(make_float2(a[4] * s2, a[5] * s2));
    __nv_bfloat162 b3 = __float22bfloat162_rn(make_float2(a[6] * s2, a[7] * s2));
    uint4 u;
    u.x = *reinterpret_cast<unsigned int*>(&b0);
    u.y = *reinterpret_cast<unsigned int*>(&b1);
    u.z = *reinterpret_cast<unsigned int*>(&b2);
    u.w = *reinterpret_cast<unsigned int*>(&b3);
    *reinterpret_cast<uint4*>(g_acc + (size_t)v * NC + c * 8) = u;
}

// Hop 2 + epilogue: out[v,:] += n[v] * sum_{s in in(v)} g_acc[s,:]
__global__ void k_gather2(float* __restrict__ out) {
    int t = blockIdx.x * blockDim.x + threadIdx.x;
    if (t >= N_NODES * 5) return;
    int v = t / 5;
    int c = t - v * 5;
    int beg = __ldg(&g_off[v]);
    int deg = __ldg(&g_deg[v]);
    const int* cp = g_csr + beg;
    float a[8] = {0, 0, 0, 0, 0, 0, 0, 0};
#pragma unroll 4
    for (int i = 0; i < deg; i++) {
        int s = __ldg(cp + i);
        acc_bf16x8(a, *reinterpret_cast<const uint4*>(g_acc + (size_t)s * NC + c * 8));
    }
    float n = __ldg(&g_norm[v]);
    float4* po = reinterpret_cast<float4*>(out + (size_t)v * NC + c * 8);
    float4 b;
    b = po[0];
    b.x = fmaf(n, a[0], b.x); b.y = fmaf(n, a[1], b.y);
    b.z = fmaf(n, a[2], b.z); b.w = fmaf(n, a[3], b.w);
    po[0] = b;
    b = po[1];
    b.x = fmaf(n, a[4], b.x); b.y = fmaf(n, a[5], b.y);
    b.z = fmaf(n, a[6], b.z); b.w = fmaf(n, a[7], b.w);
    po[1] = b;
}

// ---------------------------------------------------------------------------
extern "C" void kernel_launch(void* const* d_in, const int* in_sizes, int n_in,
                              void* d_out, int out_size) {
    const float* feat  = (const float*)d_in[0];   // [50000, 96]
    const int*   src   = (const int*)  d_in[1];   // [800000]
    const int*   dst   = (const int*)  d_in[2];   // [800000]
    const float* Wsgc  = (const float*)d_in[3];   // [128, 96]
    const float* Wlin  = (const float*)d_in[4];   // [128, 96]
    const float* Wproj = (const float*)d_in[5];   // [40, 256]
    float* out = (float*)d_out;                   // [50000, 40]

    const int gemm_smem = (2 * NF * NC + GROWS * 97) * (int)sizeof(float); // 55552
    cudaFuncSetAttribute(k_gemm, cudaFuncAttributeMaxDynamicSharedMemorySize, gemm_smem);

    k_init<<<(N_NODES + 255) / 256, 256>>>();
    k_deg <<<(N_EDGES + 255) / 256, 256>>>(dst);
    k_scan<<<(N_NODES + 255) / 256, 256>>>();
    k_fill<<<(N_EDGES + 255) / 256, 256>>>(src, dst);
    k_weights<<<dim3(NC, 2, 4), NF>>>(Wproj, Wsgc, Wlin);
    k_gemm<<<(N_NODES + GROWS - 1) / GROWS, dim3(10, 16), gemm_smem>>>(feat, out);
    k_gather1<<<(N_NODES * 5 + 255) / 256, 256>>>();
    k_gather2<<<(N_NODES * 5 + 255) / 256, 256>>>(out);
}

// round 16
// speedup vs baseline: 1.0954x; 1.0106x over previous
#include <cuda_runtime.h>
#include <cuda_bf16.h>
#include <math.h>
#include <stdint.h>

#define N_NODES   50000
#define N_EDGES   800000
#define NF        96
#define NH        128
#define NC        40
#define GROWS     64                        // rows per GEMM block
#define SCAN_BLOCKS 196                     // ceil(50000/256)
#define WEIGHT_BLOCKS 120                   // 2*4*40*96 / 256

// ---------------- device scratch (static, allocation-free) ----------------
// Symbols referenced ONLY from device code (host-side use gives shadow addr).
// INVARIANT: g_deg == 0 and g_total == 0 at entry of every kernel_launch call.
// (zero-initialized at module load; k_scan re-zeroes g_deg after reading it,
//  k_gather1 resets g_total — every call restores the invariant.)
__device__ __align__(16) __nv_bfloat16 g_t  [N_NODES * NC];  // prop state (bf16)
__device__ __align__(16) __nv_bfloat16 g_acc[N_NODES * NC];  // hop-1 result (bf16)
__device__ float g_norm[N_NODES];
__device__ int   g_deg   [N_NODES];
__device__ int   g_off   [N_NODES];
__device__ int   g_cursor[N_NODES];          // after k_fill: off + deg
__device__ int   g_total;
__device__ int   g_csr   [N_EDGES];          // src ids grouped by dst
__device__ float g_M1p[4 * NF * NC];         // K-split partials, [f][c]
__device__ float g_M2p[4 * NF * NC];

// ---------------------------------------------------------------------------
// Degree count, 4 edges/thread (4 independent ATOMG chains for latency hiding).
__global__ void k_deg(const int4* __restrict__ dst4) {
    int e4 = blockIdx.x * blockDim.x + threadIdx.x;
    if (e4 >= N_EDGES / 4) return;
    int4 d = __ldg(dst4 + e4);
    atomicAdd(&g_deg[d.x], 1);
    atomicAdd(&g_deg[d.y], 1);
    atomicAdd(&g_deg[d.z], 1);
    atomicAdd(&g_deg[d.w], 1);
}

// Fused: [blocks 0..195]  region assignment (block scan + atomic reservation),
//        cursors, norms, and g_deg restore-to-zero;
//        [blocks 196..315] folded projection weights (K-split partials).
// CSR regions only need to be disjoint, not id-ordered.
__global__ void k_scan_w(const float* __restrict__ Wp,
                         const float* __restrict__ Wsgc,
                         const float* __restrict__ Wlin) {
    if (blockIdx.x < SCAN_BLOCKS) {
        __shared__ int sh[256];
        __shared__ int base_sh;
        int i = blockIdx.x * 256 + threadIdx.x;
        int d = (i < N_NODES) ? g_deg[i] : 0;
        sh[threadIdx.x] = d;
        __syncthreads();
#pragma unroll
        for (int off = 1; off < 256; off <<= 1) {
            int t = (threadIdx.x >= off) ? sh[threadIdx.x - off] : 0;
            __syncthreads();
            sh[threadIdx.x] += t;
            __syncthreads();
        }
        if (threadIdx.x == 255) base_sh = atomicAdd(&g_total, sh[255]);
        __syncthreads();
        if (i < N_NODES) {
            int off = base_sh + sh[threadIdx.x] - d;  // exclusive + block base
            g_off[i] = off;
            g_cursor[i] = off;
            g_norm[i] = (d > 0) ? rsqrtf((float)d) : 1.0f;
            g_deg[i] = 0;                             // restore invariant
        }
    } else {
        // one folded-weight element per thread:
        // M1[c,f] = sum_h Wp[c,h]*W_lin[h,f];  M2[c,f] = sum_h Wp[c,128+h]*W_sgc[h,f]
        int idx = (blockIdx.x - SCAN_BLOCKS) * 256 + threadIdx.x;  // 0..30719
        int f = idx % NF;
        int rest = idx / NF;          // 0..319
        int c = rest % NC;
        rest /= NC;                   // 0..7
        int part = rest & 3;
        int sel = rest >> 2;
        const float* wp = Wp + c * 256 + sel * 128 + part * 32;
        const float* W  = (sel ? Wsgc : Wlin) + part * 32 * NF;
        float acc = 0.0f;
#pragma unroll
        for (int h = 0; h < 32; h++)
            acc = fmaf(__ldg(wp + h), __ldg(W + h * NF + f), acc);
        (sel ? g_M2p : g_M1p)[part * (NF * NC) + f * NC + c] = acc;
    }
}

// CSR fill, 4 edges/thread (4 independent atomic->store chains).
__global__ void k_fill(const int4* __restrict__ src4,
                       const int4* __restrict__ dst4) {
    int e4 = blockIdx.x * blockDim.x + threadIdx.x;
    if (e4 >= N_EDGES / 4) return;
    int4 s = __ldg(src4 + e4);
    int4 d = __ldg(dst4 + e4);
    int p0 = atomicAdd(&g_cursor[d.x], 1);
    int p1 = atomicAdd(&g_cursor[d.y], 1);
    int p2 = atomicAdd(&g_cursor[d.z], 1);
    int p3 = atomicAdd(&g_cursor[d.w], 1);
    g_csr[p0] = s.x;
    g_csr[p1] = s.y;
    g_csr[p2] = s.z;
    g_csr[p3] = s.w;
}

// ---- packed f32x2 helpers (FFMA2 — ptxas never emits this from C++) ----
__device__ __forceinline__ unsigned long long bcast2(float s) {
    unsigned long long r;
    asm("mov.b64 %0, {%1, %1};" : "=l"(r) : "f"(s));
    return r;
}
__device__ __forceinline__ void ffma2(unsigned long long& d,
                                      unsigned long long a,
                                      unsigned long long b) {
    asm("fma.rn.f32x2 %0, %1, %2, %0;" : "+l"(d) : "l"(a), "l"(b));
}
__device__ __forceinline__ float2 unpack2(unsigned long long v) {
    float2 f;
    asm("mov.b64 {%0, %1}, %2;" : "=f"(f.x), "=f"(f.y) : "l"(v));
    return f;
}

// Fused dual GEMM (packed f32x2 mainloop), 4 rows x 4 cols x 2 matrices/thread:
//   out[v,:] = feat[v,:] @ M1^T            (base term fp32, straight to d_out)
//   g_t[v,:] = bf16( norm[v] * (feat[v,:]@M2^T) )
__global__ void __launch_bounds__(160) k_gemm(const float* __restrict__ feat,
                                              float* __restrict__ out) {
    extern __shared__ float sh[];
    float* sM1 = sh;                    // [NF*NC]
    float* sM2 = sh + NF * NC;          // [NF*NC]
    float* sF  = sh + 2 * NF * NC;      // [GROWS*97]

    const int tid = threadIdx.y * 10 + threadIdx.x;
    for (int i = tid; i < NF * NC; i += 160) {
        sM1[i] = g_M1p[i] + g_M1p[i + 3840] + g_M1p[i + 7680] + g_M1p[i + 11520];
        sM2[i] = g_M2p[i] + g_M2p[i + 3840] + g_M2p[i + 7680] + g_M2p[i + 11520];
    }

    const int row0 = blockIdx.x * GROWS;
    for (int i = tid; i < GROWS * NF; i += 160) {
        int r = i / NF, f = i - r * NF;
        int v = row0 + r;
        sF[r * 97 + f] = (v < N_NODES) ? feat[(size_t)v * NF + f] : 0.0f;
    }
    __syncthreads();

    const int cx = threadIdx.x;            // col group: 4*cx .. 4*cx+3
    const int r0 = threadIdx.y * 4;        // rows r0 .. r0+3

    unsigned long long a1lo[4] = {0, 0, 0, 0}, a1hi[4] = {0, 0, 0, 0};
    unsigned long long a2lo[4] = {0, 0, 0, 0}, a2hi[4] = {0, 0, 0, 0};

#pragma unroll 4
    for (int f = 0; f < NF; f++) {
        const ulonglong2 m1 = *reinterpret_cast<const ulonglong2*>(sM1 + f * NC + cx * 4);
        const ulonglong2 m2 = *reinterpret_cast<const ulonglong2*>(sM2 + f * NC + cx * 4);
#pragma unroll
        for (int r = 0; r < 4; r++) {
            const unsigned long long fb = bcast2(sF[(r0 + r) * 97 + f]);
            ffma2(a1lo[r], fb, m1.x);
            ffma2(a1hi[r], fb, m1.y);
            ffma2(a2lo[r], fb, m2.x);
            ffma2(a2hi[r], fb, m2.y);
        }
    }

#pragma unroll
    for (int r = 0; r < 4; r++) {
        const int v = row0 + r0 + r;
        if (v < N_NODES) {
            float n = g_norm[v];
            float2 x0 = unpack2(a1lo[r]), x1 = unpack2(a1hi[r]);
            *reinterpret_cast<float4*>(out + (size_t)v * NC + cx * 4) =
                make_float4(x0.x, x0.y, x1.x, x1.y);
            float2 y0 = unpack2(a2lo[r]), y1 = unpack2(a2hi[r]);
            __nv_bfloat162 b0 = __float22bfloat162_rn(make_float2(y0.x * n, y0.y * n));
            __nv_bfloat162 b1 = __float22bfloat162_rn(make_float2(y1.x * n, y1.y * n));
            uint2 u;
            u.x = *reinterpret_cast<unsigned int*>(&b0);
            u.y = *reinterpret_cast<unsigned int*>(&b1);
            *reinterpret_cast<uint2*>(g_t + (size_t)v * NC + cx * 4) = u;
        }
    }
}

__device__ __forceinline__ void acc_bf16x8(float* a, uint4 p) {
    float2 f;
    f = __bfloat1622float2(*reinterpret_cast<__nv_bfloat162*>(&p.x)); a[0] += f.x; a[1] += f.y;
    f = __bfloat1622float2(*reinterpret_cast<__nv_bfloat162*>(&p.y)); a[2] += f.x; a[3] += f.y;
    f = __bfloat1622float2(*reinterpret_cast<__nv_bfloat162*>(&p.z)); a[4] += f.x; a[5] += f.y;
    f = __bfloat1622float2(*reinterpret_cast<__nv_bfloat162*>(&p.w)); a[6] += f.x; a[7] += f.y;
}

// Hop 1 (CSR gather, chunk-parallel, bf16 source): 5 lanes per node, 8 classes
// each. Per edge the 5-lane group loads one contiguous 80B bf16 row; fp32
// accumulate; store back as bf16 with n^2 folded in. deg = cursor - off.
__global__ void k_gather1() {
    int t = blockIdx.x * blockDim.x + threadIdx.x;
    if (t == 0) g_total = 0;                   // restore invariant for next call
    if (t >= N_NODES * 5) return;
    int v = t / 5;
    int c = t - v * 5;
    int beg = __ldg(&g_off[v]);
    int end = __ldg(&g_cursor[v]);
    const int* cp = g_csr;
    float a[8] = {0, 0, 0, 0, 0, 0, 0, 0};
#pragma unroll 4
    for (int i = beg; i < end; i++) {
        int s = __ldg(cp + i);
        acc_bf16x8(a, *reinterpret_cast<const uint4*>(g_t + (size_t)s * NC + c * 8));
    }
    float n = __ldg(&g_norm[v]);
    float s2 = n * n;
    __nv_bfloat162 b0 = __float22bfloat162_rn(make_float2(a[0] * s2, a[1] * s2));
    __nv_bfloat162 b1 = __float22bfloat162_rn(make_float2(a[2] * s2, a[3] * s2));
    __nv_bfloat162 b2 = __float22bfloat162_rn(make_float2(a[4] * s2, a[5] * s2));
    __nv_bfloat162 b3 = __float22bfloat162_rn(make_float2(a[6] * s2, a[7] * s2));
    uint4 u;
    u.x = *reinterpret_cast<unsigned int*>(&b0);
    u.y = *reinterpret_cast<unsigned int*>(&b1);
    u.z = *reinterpret_cast<unsigned int*>(&b2);
    u.w = *reinterpret_cast<unsigned int*>(&b3);
    *reinterpret_cast<uint4*>(g_acc + (size_t)v * NC + c * 8) = u;
}

// Hop 2 + epilogue: out[v,:] += n[v] * sum_{s in in(v)} g_acc[s,:]
__global__ void k_gather2(float* __restrict__ out) {
    int t = blockIdx.x * blockDim.x + threadIdx.x;
    if (t >= N_NODES * 5) return;
    int v = t / 5;
    int c = t - v * 5;
    int beg = __ldg(&g_off[v]);
    int end = __ldg(&g_cursor[v]);
    const int* cp = g_csr;
    float a[8] = {0, 0, 0, 0, 0, 0, 0, 0};
#pragma unroll 4
    for (int i = beg; i < end; i++) {
        int s = __ldg(cp + i);
        acc_bf16x8(a, *reinterpret_cast<const uint4*>(g_acc + (size_t)s * NC + c * 8));
    }
    float n = __ldg(&g_norm[v]);
    float4* po = reinterpret_cast<float4*>(out + (size_t)v * NC + c * 8);
    float4 b;
    b = po[0];
    b.x = fmaf(n, a[0], b.x); b.y = fmaf(n, a[1], b.y);
    b.z = fmaf(n, a[2], b.z); b.w = fmaf(n, a[3], b.w);
    po[0] = b;
    b = po[1];
    b.x = fmaf(n, a[4], b.x); b.y = fmaf(n, a[5], b.y);
    b.z = fmaf(n, a[6], b.z); b.w = fmaf(n, a[7], b.w);
    po[1] = b;
}

// ---------------------------------------------------------------------------
extern "C" void kernel_launch(void* const* d_in, const int* in_sizes, int n_in,
                              void* d_out, int out_size) {
    const float* feat  = (const float*)d_in[0];   // [50000, 96]
    const int*   src   = (const int*)  d_in[1];   // [800000]
    const int*   dst   = (const int*)  d_in[2];   // [800000]
    const float* Wsgc  = (const float*)d_in[3];   // [128, 96]
    const float* Wlin  = (const float*)d_in[4];   // [128, 96]
    const float* Wproj = (const float*)d_in[5];   // [40, 256]
    float* out = (float*)d_out;                   // [50000, 40]

    const int gemm_smem = (2 * NF * NC + GROWS * 97) * (int)sizeof(float); // 55552
    cudaFuncSetAttribute(k_gemm, cudaFuncAttributeMaxDynamicSharedMemorySize, gemm_smem);

    k_deg   <<<(N_EDGES / 4 + 255) / 256, 256>>>((const int4*)dst);
    k_scan_w<<<SCAN_BLOCKS + WEIGHT_BLOCKS, 256>>>(Wproj, Wsgc, Wlin);
    k_fill  <<<(N_EDGES / 4 + 255) / 256, 256>>>((const int4*)src, (const int4*)dst);
    k_gemm  <<<(N_NODES + GROWS - 1) / GROWS, dim3(10, 16), gemm_smem>>>(feat, out);
    k_gather1<<<(N_NODES * 5 + 255) / 256, 256>>>();
    k_gather2<<<(N_NODES * 5 + 255) / 256, 256>>>(out);
}

// round 17
// speedup vs baseline: 1.1099x; 1.0133x over previous
#include <cuda_runtime.h>
#include <cuda_bf16.h>
#include <math.h>
#include <stdint.h>

#define N_NODES   50000
#define N_EDGES   800000
#define NF        96
#define NH        128
#define NC        40
#define GROWS     64                        // rows per GEMM block
#define SCAN_BLOCKS 196                     // ceil(50000/256)
#define WEIGHT_BLOCKS 120                   // 2*4*40*96 / 256

// ---------------- device scratch (static, allocation-free) ----------------
// Symbols referenced ONLY from device code (host-side use gives shadow addr).
// INVARIANT: g_deg == 0 and g_total == 0 at entry of every kernel_launch call.
// (zero-initialized at module load; k_scan re-zeroes g_deg after reading it,
//  k_gather1 resets g_total — every call restores the invariant.)
__device__ __align__(16) __nv_bfloat16 g_t  [N_NODES * NC];  // prop state (bf16)
__device__ __align__(16) __nv_bfloat16 g_acc[N_NODES * NC];  // hop-1 result (bf16)
__device__ float g_norm[N_NODES];
__device__ int   g_deg   [N_NODES];
__device__ int   g_off   [N_NODES];
__device__ int   g_cursor[N_NODES];          // after k_fill: off + deg
__device__ int   g_total;
__device__ int   g_csr   [N_EDGES];          // src ids grouped by dst
__device__ float g_M1p[4 * NF * NC];         // K-split partials, [f][c]
__device__ float g_M2p[4 * NF * NC];

// ---------------------------------------------------------------------------
// Degree count, 4 edges/thread (4 independent ATOMG chains for latency hiding).
__global__ void k_deg(const int4* __restrict__ dst4) {
    int e4 = blockIdx.x * blockDim.x + threadIdx.x;
    if (e4 >= N_EDGES / 4) return;
    int4 d = __ldg(dst4 + e4);
    atomicAdd(&g_deg[d.x], 1);
    atomicAdd(&g_deg[d.y], 1);
    atomicAdd(&g_deg[d.z], 1);
    atomicAdd(&g_deg[d.w], 1);
}

// Fused: [blocks 0..195]  region assignment (block scan + atomic reservation),
//        cursors, norms, and g_deg restore-to-zero;
//        [blocks 196..315] folded projection weights (K-split partials).
// CSR regions only need to be disjoint, not id-ordered.
__global__ void k_scan_w(const float* __restrict__ Wp,
                         const float* __restrict__ Wsgc,
                         const float* __restrict__ Wlin) {
    if (blockIdx.x < SCAN_BLOCKS) {
        __shared__ int sh[256];
        __shared__ int base_sh;
        int i = blockIdx.x * 256 + threadIdx.x;
        int d = (i < N_NODES) ? g_deg[i] : 0;
        sh[threadIdx.x] = d;
        __syncthreads();
#pragma unroll
        for (int off = 1; off < 256; off <<= 1) {
            int t = (threadIdx.x >= off) ? sh[threadIdx.x - off] : 0;
            __syncthreads();
            sh[threadIdx.x] += t;
            __syncthreads();
        }
        if (threadIdx.x == 255) base_sh = atomicAdd(&g_total, sh[255]);
        __syncthreads();
        if (i < N_NODES) {
            int off = base_sh + sh[threadIdx.x] - d;  // exclusive + block base
            g_off[i] = off;
            g_cursor[i] = off;
            g_norm[i] = (d > 0) ? rsqrtf((float)d) : 1.0f;
            g_deg[i] = 0;                             // restore invariant
        }
    } else {
        // one folded-weight element per thread:
        // M1[c,f] = sum_h Wp[c,h]*W_lin[h,f];  M2[c,f] = sum_h Wp[c,128+h]*W_sgc[h,f]
        int idx = (blockIdx.x - SCAN_BLOCKS) * 256 + threadIdx.x;  // 0..30719
        int f = idx % NF;
        int rest = idx / NF;          // 0..319
        int c = rest % NC;
        rest /= NC;                   // 0..7
        int part = rest & 3;
        int sel = rest >> 2;
        const float* wp = Wp + c * 256 + sel * 128 + part * 32;
        const float* W  = (sel ? Wsgc : Wlin) + part * 32 * NF;
        float acc = 0.0f;
#pragma unroll
        for (int h = 0; h < 32; h++)
            acc = fmaf(__ldg(wp + h), __ldg(W + h * NF + f), acc);
        (sel ? g_M2p : g_M1p)[part * (NF * NC) + f * NC + c] = acc;
    }
}

// CSR fill, 4 edges/thread (4 independent atomic->store chains).
__global__ void k_fill(const int4* __restrict__ src4,
                       const int4* __restrict__ dst4) {
    int e4 = blockIdx.x * blockDim.x + threadIdx.x;
    if (e4 >= N_EDGES / 4) return;
    int4 s = __ldg(src4 + e4);
    int4 d = __ldg(dst4 + e4);
    int p0 = atomicAdd(&g_cursor[d.x], 1);
    int p1 = atomicAdd(&g_cursor[d.y], 1);
    int p2 = atomicAdd(&g_cursor[d.z], 1);
    int p3 = atomicAdd(&g_cursor[d.w], 1);
    g_csr[p0] = s.x;
    g_csr[p1] = s.y;
    g_csr[p2] = s.z;
    g_csr[p3] = s.w;
}

// ---- packed f32x2 helpers (FFMA2 — ptxas never emits this from C++) ----
__device__ __forceinline__ unsigned long long bcast2(float s) {
    unsigned long long r;
    asm("mov.b64 %0, {%1, %1};" : "=l"(r) : "f"(s));
    return r;
}
__device__ __forceinline__ void ffma2(unsigned long long& d,
                                      unsigned long long a,
                                      unsigned long long b) {
    asm("fma.rn.f32x2 %0, %1, %2, %0;" : "+l"(d) : "l"(a), "l"(b));
}
__device__ __forceinline__ float2 unpack2(unsigned long long v) {
    float2 f;
    asm("mov.b64 {%0, %1}, %2;" : "=f"(f.x), "=f"(f.y) : "l"(v));
    return f;
}

// Fused dual GEMM (packed f32x2 mainloop), 4 rows x 4 cols x 2 matrices/thread:
//   out[v,:] = feat[v,:] @ M1^T            (base term fp32, straight to d_out)
//   g_t[v,:] = bf16( norm[v] * (feat[v,:]@M2^T) )
__global__ void __launch_bounds__(160) k_gemm(const float* __restrict__ feat,
                                              float* __restrict__ out) {
    extern __shared__ float sh[];
    float* sM1 = sh;                    // [NF*NC]
    float* sM2 = sh + NF * NC;          // [NF*NC]
    float* sF  = sh + 2 * NF * NC;      // [GROWS*97]

    const int tid = threadIdx.y * 10 + threadIdx.x;
    for (int i = tid; i < NF * NC; i += 160) {
        sM1[i] = g_M1p[i] + g_M1p[i + 3840] + g_M1p[i + 7680] + g_M1p[i + 11520];
        sM2[i] = g_M2p[i] + g_M2p[i + 3840] + g_M2p[i + 7680] + g_M2p[i + 11520];
    }

    const int row0 = blockIdx.x * GROWS;
    for (int i = tid; i < GROWS * NF; i += 160) {
        int r = i / NF, f = i - r * NF;
        int v = row0 + r;
        sF[r * 97 + f] = (v < N_NODES) ? feat[(size_t)v * NF + f] : 0.0f;
    }
    __syncthreads();

    const int cx = threadIdx.x;            // col group: 4*cx .. 4*cx+3
    const int r0 = threadIdx.y * 4;        // rows r0 .. r0+3

    unsigned long long a1lo[4] = {0, 0, 0, 0}, a1hi[4] = {0, 0, 0, 0};
    unsigned long long a2lo[4] = {0, 0, 0, 0}, a2hi[4] = {0, 0, 0, 0};

#pragma unroll 4
    for (int f = 0; f < NF; f++) {
        const ulonglong2 m1 = *reinterpret_cast<const ulonglong2*>(sM1 + f * NC + cx * 4);
        const ulonglong2 m2 = *reinterpret_cast<const ulonglong2*>(sM2 + f * NC + cx * 4);
#pragma unroll
        for (int r = 0; r < 4; r++) {
            const unsigned long long fb = bcast2(sF[(r0 + r) * 97 + f]);
            ffma2(a1lo[r], fb, m1.x);
            ffma2(a1hi[r], fb, m1.y);
            ffma2(a2lo[r], fb, m2.x);
            ffma2(a2hi[r], fb, m2.y);
        }
    }

#pragma unroll
    for (int r = 0; r < 4; r++) {
        const int v = row0 + r0 + r;
        if (v < N_NODES) {
            float n = g_norm[v];
            float2 x0 = unpack2(a1lo[r]), x1 = unpack2(a1hi[r]);
            *reinterpret_cast<float4*>(out + (size_t)v * NC + cx * 4) =
                make_float4(x0.x, x0.y, x1.x, x1.y);
            float2 y0 = unpack2(a2lo[r]), y1 = unpack2(a2hi[r]);
            __nv_bfloat162 b0 = __float22bfloat162_rn(make_float2(y0.x * n, y0.y * n));
            __nv_bfloat162 b1 = __float22bfloat162_rn(make_float2(y1.x * n, y1.y * n));
            uint2 u;
            u.x = *reinterpret_cast<unsigned int*>(&b0);
            u.y = *reinterpret_cast<unsigned int*>(&b1);
            *reinterpret_cast<uint2*>(g_t + (size_t)v * NC + cx * 4) = u;
        }
    }
}

__device__ __forceinline__ void acc_bf16x8(float* a, uint4 p) {
    float2 f;
    f = __bfloat1622float2(*reinterpret_cast<__nv_bfloat162*>(&p.x)); a[0] += f.x; a[1] += f.y;
    f = __bfloat1622float2(*reinterpret_cast<__nv_bfloat162*>(&p.y)); a[2] += f.x; a[3] += f.y;
    f = __bfloat1622float2(*reinterpret_cast<__nv_bfloat162*>(&p.z)); a[4] += f.x; a[5] += f.y;
    f = __bfloat1622float2(*reinterpret_cast<__nv_bfloat162*>(&p.w)); a[6] += f.x; a[7] += f.y;
}

// Hop 1 (CSR gather, chunk-parallel, bf16 source): 5 lanes per node, 8 classes
// each. Per edge the 5-lane group loads one contiguous 80B bf16 row; fp32
// accumulate; store back as bf16 with n^2 folded in. deg = cursor - off.
__global__ void k_gather1() {
    int t = blockIdx.x * blockDim.x + threadIdx.x;
    if (t == 0) g_total = 0;                   // restore invariant for next call
    if (t >= N_NODES * 5) return;
    int v = t / 5;
    int c = t - v * 5;
    int beg = __ldg(&g_off[v]);
    int end = __ldg(&g_cursor[v]);
    const int* cp = g_csr;
    float a[8] = {0, 0, 0, 0, 0, 0, 0, 0};
#pragma unroll 4
    for (int i = beg; i < end; i++) {
        int s = __ldg(cp + i);
        acc_bf16x8(a, *reinterpret_cast<const uint4*>(g_t + (size_t)s * NC + c * 8));
    }
    float n = __ldg(&g_norm[v]);
    float s2 = n * n;
    __nv_bfloat162 b0 = __float22bfloat162_rn(make_float2(a[0] * s2, a[1] * s2));
    __nv_bfloat162 b1 = __float22bfloat162_rn(make_float2(a[2] * s2, a[3] * s2));
    __nv_bfloat162 b2 = __float22bfloat162_rn(make_float2(a[4] * s2, a[5] * s2));
    __nv_bfloat162 b3 = __float22bfloat162_rn(make_float2(a[6] * s2, a[7] * s2));
    uint4 u;
    u.x = *reinterpret_cast<unsigned int*>(&b0);
    u.y = *reinterpret_cast<unsigned int*>(&b1);
    u.z = *reinterpret_cast<unsigned int*>(&b2);
    u.w = *reinterpret_cast<unsigned int*>(&b3);
    *reinterpret_cast<uint4*>(g_acc + (size_t)v * NC + c * 8) = u;
}

// Hop 2 + epilogue: out[v,:] += n[v] * sum_{s in in(v)} g_acc[s,:]
__global__ void k_gather2(float* __restrict__ out) {
    int t = blockIdx.x * blockDim.x + threadIdx.x;
    if (t >= N_NODES * 5) return;
    int v = t / 5;
    int c = t - v * 5;
    int beg = __ldg(&g_off[v]);
    int end = __ldg(&g_cursor[v]);
    const int* cp = g_csr;
    float a[8] = {0, 0, 0, 0, 0, 0, 0, 0};
#pragma unroll 4
    for (int i = beg; i < end; i++) {
        int s = __ldg(cp + i);
        acc_bf16x8(a, *reinterpret_cast<const uint4*>(g_acc + (size_t)s * NC + c * 8));
    }
    float n = __ldg(&g_norm[v]);
    float4* po = reinterpret_cast<float4*>(out + (size_t)v * NC + c * 8);
    float4 b;
    b = po[0];
    b.x = fmaf(n, a[0], b.x); b.y = fmaf(n, a[1], b.y);
    b.z = fmaf(n, a[2], b.z); b.w = fmaf(n, a[3], b.w);
    po[0] = b;
    b = po[1];
    b.x = fmaf(n, a[4], b.x); b.y = fmaf(n, a[5], b.y);
    b.z = fmaf(n, a[6], b.z); b.w = fmaf(n, a[7], b.w);
    po[1] = b;
}

// ---------------------------------------------------------------------------
extern "C" void kernel_launch(void* const* d_in, const int* in_sizes, int n_in,
                              void* d_out, int out_size) {
    const float* feat  = (const float*)d_in[0];   // [50000, 96]
    const int*   src   = (const int*)  d_in[1];   // [800000]
    const int*   dst   = (const int*)  d_in[2];   // [800000]
    const float* Wsgc  = (const float*)d_in[3];   // [128, 96]
    const float* Wlin  = (const float*)d_in[4];   // [128, 96]
    const float* Wproj = (const float*)d_in[5];   // [40, 256]
    float* out = (float*)d_out;                   // [50000, 40]

    const int gemm_smem = (2 * NF * NC + GROWS * 97) * (int)sizeof(float); // 55552
    cudaFuncSetAttribute(k_gemm, cudaFuncAttributeMaxDynamicSharedMemorySize, gemm_smem);

    k_deg   <<<(N_EDGES / 4 + 255) / 256, 256>>>((const int4*)dst);
    k_scan_w<<<SCAN_BLOCKS + WEIGHT_BLOCKS, 256>>>(Wproj, Wsgc, Wlin);
    k_fill  <<<(N_EDGES / 4 + 255) / 256, 256>>>((const int4*)src, (const int4*)dst);
    k_gemm  <<<(N_NODES + GROWS - 1) / GROWS, dim3(10, 16), gemm_smem>>>(feat, out);
    k_gather1<<<(N_NODES * 5 + 255) / 256, 256>>>();
    k_gather2<<<(N_NODES * 5 + 255) / 256, 256>>>(out);
}